// round 1
// baseline (speedup 1.0000x reference)
#include <cuda_runtime.h>
#include <cuda_bf16.h>

#define D       128
#define MAXN    100000
#define MAXE    1600000

// Scratch (static __device__ arrays: no allocation allowed)
__device__ int   g_deg[MAXN];
__device__ float g_scale[MAXN];                   // rsqrt(deg+1)
__device__ float g_inv[MAXN];                     // 1/max(deg,1)
__device__ float g_accum[(size_t)MAXN * D];       // 51.2 MB

// ---------------------------------------------------------------------------
// Zero scratch: accum (as float4) and deg
// ---------------------------------------------------------------------------
__global__ void zero_kernel(int n_nodes) {
    int i = blockIdx.x * blockDim.x + threadIdx.x;
    int total4 = n_nodes * (D / 4);
    if (i < total4) ((float4*)g_accum)[i] = make_float4(0.f, 0.f, 0.f, 0.f);
    if (i < n_nodes) g_deg[i] = 0;
}

// ---------------------------------------------------------------------------
// In-degree count
// ---------------------------------------------------------------------------
__global__ void deg_kernel(const int* __restrict__ dst, int E) {
    int i = blockIdx.x * blockDim.x + threadIdx.x;
    if (i < E) atomicAdd(&g_deg[dst[i]], 1);
}

// ---------------------------------------------------------------------------
// Per-node scale factors
// ---------------------------------------------------------------------------
__global__ void scale_kernel(int n) {
    int i = blockIdx.x * blockDim.x + threadIdx.x;
    if (i < n) {
        int d = g_deg[i];
        g_scale[i] = rsqrtf((float)d + 1.0f);
        g_inv[i]   = 1.0f / (float)(d > 0 ? d : 1);
    }
}

// ---------------------------------------------------------------------------
// Edge aggregation: one warp per edge.
// Each lane: gather one float4 of feat[src], scale, red.add.v4 into accum[dst].
// ---------------------------------------------------------------------------
__global__ void scatter_kernel(const float* __restrict__ feat,
                               const int*   __restrict__ src,
                               const int*   __restrict__ dst,
                               int E) {
    int t = blockIdx.x * blockDim.x + threadIdx.x;
    int e = t >> 5;
    int lane = t & 31;
    if (e >= E) return;

    int s = __ldg(src + e);
    int d = __ldg(dst + e);
    float sc = g_scale[s];

    float4 v = __ldg((const float4*)(feat + (size_t)s * D) + lane);
    v.x *= sc; v.y *= sc; v.z *= sc; v.w *= sc;

    float* p = g_accum + (size_t)d * D + lane * 4;
    asm volatile("red.global.add.v4.f32 [%0], {%1,%2,%3,%4};"
                 :: "l"(p), "f"(v.x), "f"(v.y), "f"(v.z), "f"(v.w)
                 : "memory");
}

// ---------------------------------------------------------------------------
// GEMM: out[n, 128] = (accum[n,:] * inv[n]) @ W[128,128] + b
// BM=128, BN=128, BK=16, 256 threads, 8x8 register tiles.
// ---------------------------------------------------------------------------
#define BM 128
#define BN 128
#define BK 16
#define TM 8
#define TN 8

__global__ __launch_bounds__(256, 2)
void gemm_kernel(const float* __restrict__ W,
                 const float* __restrict__ bias,
                 float* __restrict__ out,
                 int n) {
    __shared__ float As[BK][BM + 4];
    __shared__ float Ws[BK][BN];

    int block_row = blockIdx.x * BM;
    int tid = threadIdx.x;
    int tx = tid & 15;          // 0..15 -> cols
    int ty = tid >> 4;          // 0..15 -> rows

    float c[TM][TN];
#pragma unroll
    for (int i = 0; i < TM; i++)
#pragma unroll
        for (int j = 0; j < TN; j++) c[i][j] = 0.f;

    for (int k0 = 0; k0 < D; k0 += BK) {
        // Load A tile (BM x BK), applying 1/deg at load. 512 float4 units.
#pragma unroll
        for (int it = 0; it < 2; it++) {
            int idx = tid + it * 256;       // 0..511
            int row = idx >> 2;             // 0..127
            int k4  = (idx & 3) * 4;        // 0,4,8,12
            int grow = block_row + row;
            float4 v = make_float4(0.f, 0.f, 0.f, 0.f);
            float iv = 0.f;
            if (grow < n) {
                v  = *(const float4*)&g_accum[(size_t)grow * D + k0 + k4];
                iv = g_inv[grow];
            }
            As[k4 + 0][row] = v.x * iv;
            As[k4 + 1][row] = v.y * iv;
            As[k4 + 2][row] = v.z * iv;
            As[k4 + 3][row] = v.w * iv;
        }
        // Load W tile (BK x BN). 512 float4 units.
#pragma unroll
        for (int it = 0; it < 2; it++) {
            int idx = tid + it * 256;       // 0..511
            int k  = idx >> 5;              // 0..15
            int c4 = (idx & 31) * 4;        // 0..124
            float4 v = __ldg((const float4*)&W[(size_t)(k0 + k) * D + c4]);
            *(float4*)&Ws[k][c4] = v;
        }
        __syncthreads();

#pragma unroll
        for (int k = 0; k < BK; k++) {
            float a[TM], w[TN];
#pragma unroll
            for (int i = 0; i < TM; i++) a[i] = As[k][ty * TM + i];
#pragma unroll
            for (int j = 0; j < TN; j++) w[j] = Ws[k][tx * TN + j];
#pragma unroll
            for (int i = 0; i < TM; i++)
#pragma unroll
                for (int j = 0; j < TN; j++)
                    c[i][j] = fmaf(a[i], w[j], c[i][j]);
        }
        __syncthreads();
    }

    // Epilogue: add bias, write out
#pragma unroll
    for (int i = 0; i < TM; i++) {
        int row = block_row + ty * TM + i;
        if (row < n) {
#pragma unroll
            for (int j = 0; j < TN; j += 4) {
                int col = tx * TN + j;
                float4 r;
                r.x = c[i][j + 0] + __ldg(&bias[col + 0]);
                r.y = c[i][j + 1] + __ldg(&bias[col + 1]);
                r.z = c[i][j + 2] + __ldg(&bias[col + 2]);
                r.w = c[i][j + 3] + __ldg(&bias[col + 3]);
                *(float4*)&out[(size_t)row * D + col] = r;
            }
        }
    }
}

// ---------------------------------------------------------------------------
extern "C" void kernel_launch(void* const* d_in, const int* in_sizes, int n_in,
                              void* d_out, int out_size) {
    const float* feature = (const float*)d_in[0];
    const float* W       = (const float*)d_in[1];
    const float* bias    = (const float*)d_in[2];
    const int*   src     = (const int*)d_in[3];
    const int*   dst     = (const int*)d_in[4];
    float*       out     = (float*)d_out;

    int N = in_sizes[0] / D;
    int E = in_sizes[3];

    // 1) zero scratch
    {
        int total4 = N * (D / 4);
        int threads = 256;
        int blocks = (total4 + threads - 1) / threads;
        zero_kernel<<<blocks, threads>>>(N);
    }
    // 2) in-degree
    {
        int threads = 256;
        int blocks = (E + threads - 1) / threads;
        deg_kernel<<<blocks, threads>>>(dst, E);
    }
    // 3) per-node scale factors
    {
        int threads = 256;
        int blocks = (N + threads - 1) / threads;
        scale_kernel<<<blocks, threads>>>(N);
    }
    // 4) edge aggregation (one warp per edge)
    {
        int threads = 256;
        long long total = (long long)E * 32;
        int blocks = (int)((total + threads - 1) / threads);
        scatter_kernel<<<blocks, threads>>>(feature, src, dst, E);
    }
    // 5) GEMM + bias
    {
        int blocks = (N + BM - 1) / BM;
        gemm_kernel<<<blocks, 256>>>(W, bias, out, N);
    }
}